// round 2
// baseline (speedup 1.0000x reference)
#include <cuda_runtime.h>
#include <cuda_bf16.h>
#include <cstdint>

#define NB 2
#define NROWS 8192
#define FDIM 512
#define TIL 128
#define NTILES 64      // 8192/128
#define CAND_T 16
#define FEATS_ELEMS ((long)NB*NROWS*FDIM)          // 8388608
#define ADJ_ELEMS   ((long)NB*NROWS*NROWS)         // 134217728

// ---------------- scratch (device globals: allowed) ----------------
__device__ __align__(16) __nv_bfloat16 g_fb[NB*NROWS*FDIM];          // 16MB bf16 feats
__device__ float g_sq[NB*NROWS];                                     // row sq norms (bf16 path only)
__device__ float g_cd[(long)NB*NTILES*CAND_T*NROWS];                 // 64MB cand dists
__device__ int   g_ci[(long)NB*NTILES*CAND_T*NROWS];                 // 64MB cand idx
__device__ int   g_topi[NB*NROWS*16];                                // merged top-16 idx

__device__ __forceinline__ float finf() { return __int_as_float(0x7f800000); }

// ---------------- 1. patch extraction ----------------
// image [2,1,256,256,64] -> feats [2,8192,512] (fp32 to d_out, bf16 to scratch)
// p = (hb*32+wb)*8+db ; f = (ph*8+pw)*8+pd
__global__ void patch_kernel(const float* __restrict__ img, float* __restrict__ feats) {
    int idx = blockIdx.x * blockDim.x + threadIdx.x;   // < 2*8192*64
    int fc = idx & 63;
    int t  = idx >> 6;
    int p  = t & 8191;
    int b  = t >> 13;
    int ph = fc >> 3, pw = fc & 7;
    int db = p & 7, wb = (p >> 3) & 31, hb = p >> 8;
    const float4* src = (const float4*)(img + (long)b*4194304
                          + (long)(hb*8+ph)*16384 + (long)(wb*8+pw)*64 + db*8);
    float4 v0 = src[0], v1 = src[1];
    long o = (long)t*FDIM + fc*8;
    float4* dst = (float4*)(feats + o);
    dst[0] = v0; dst[1] = v1;
    __nv_bfloat162* bp = (__nv_bfloat162*)(g_fb + o);
    bp[0] = __floats2bfloat162_rn(v0.x, v0.y);
    bp[1] = __floats2bfloat162_rn(v0.z, v0.w);
    bp[2] = __floats2bfloat162_rn(v1.x, v1.y);
    bp[3] = __floats2bfloat162_rn(v1.z, v1.w);
}

// ---------------- 2. squared norms (one warp per row, fp32 — candidate stage only) ----------------
__global__ void sqnorm_kernel(const float* __restrict__ feats) {
    int row = blockIdx.x * 8 + (threadIdx.x >> 5);
    int lane = threadIdx.x & 31;
    const float4* f = (const float4*)(feats + (long)row*FDIM);
    float s = 0.f;
    #pragma unroll
    for (int i = 0; i < 4; i++) {
        float4 v = f[lane + i*32];
        s = fmaf(v.x,v.x, fmaf(v.y,v.y, fmaf(v.z,v.z, fmaf(v.w,v.w, s))));
    }
    #pragma unroll
    for (int o = 16; o; o >>= 1) s += __shfl_xor_sync(0xffffffffu, s, o);
    if (!lane) g_sq[row] = s;
}

// ---------------- 3. zero the adjacency region ----------------
__global__ void zero_kernel(float4* __restrict__ p, long n4) {
    long i = blockIdx.x * (long)blockDim.x + threadIdx.x;
    long stride = gridDim.x * (long)blockDim.x;
    float4 z = make_float4(0.f, 0.f, 0.f, 0.f);
    for (; i < n4; i += stride) p[i] = z;
}

// ---------------- 4. bf16 mma.sync GEMM + fused per-tile top-16 ----------------
// CTA: 128x128 tile, K=512, BK=32, 256 threads (8 warps, warp tile 32m x 64n)
#define LDK 40   // smem row stride in bf16 (80B: 16B-aligned, conflict-free mod 32 banks)
__global__ __launch_bounds__(256) void gemm_topk_kernel() {
    __shared__ __align__(16) char smraw[33280];            // union: A/B tiles | d2 half-tile
    __shared__ float sqAs[128], sqBs[128];
    __nv_bfloat16* smA = (__nv_bfloat16*)smraw;
    __nv_bfloat16* smB = smA + 128*LDK;
    float* smd = (float*)smraw;                            // 128 x 65 fp32

    int nt = blockIdx.x, mt = blockIdx.y, bz = blockIdx.z;
    int tid = threadIdx.x;
    int lane = tid & 31, wid = tid >> 5;
    int wm = wid >> 1, wn = wid & 1;

    const __nv_bfloat16* Ag = g_fb + ((long)bz*NROWS + mt*TIL) * FDIM;
    const __nv_bfloat16* Bg = g_fb + ((long)bz*NROWS + nt*TIL) * FDIM;

    if (tid < 128) sqAs[tid] = g_sq[bz*NROWS + mt*TIL + tid];
    else           sqBs[tid-128] = g_sq[bz*NROWS + nt*TIL + (tid-128)];

    float acc[2][8][4];
    #pragma unroll
    for (int a = 0; a < 2; a++)
        #pragma unroll
        for (int b = 0; b < 8; b++)
            #pragma unroll
            for (int c = 0; c < 4; c++) acc[a][b][c] = 0.f;

    // tile load mapping: 2 threads/row, 2 x uint4 (32B) each
    int lr = tid >> 1, lh = tid & 1;
    const uint4* A4 = (const uint4*)Ag;
    const uint4* B4 = (const uint4*)Bg;
    int lbase = lr*64 + lh*2;                 // uint4 units (row = 64 uint4)
    uint4* sA4 = (uint4*)(smA + lr*LDK + lh*16);
    uint4* sB4 = (uint4*)(smB + lr*LDK + lh*16);

    uint4 va0 = A4[lbase], va1 = A4[lbase+1];
    uint4 vb0 = B4[lbase], vb1 = B4[lbase+1];
    sA4[0]=va0; sA4[1]=va1; sB4[0]=vb0; sB4[1]=vb1;
    __syncthreads();

    // ldmatrix address components
    int arow = wm*32 + (lane & 15);                       // + mi*16
    int acol = (lane >> 4) * 8;                           // + k0
    int brow = wn*64 + (lane & 7) + (lane >> 4) * 8;      // + p*16
    int bcol = ((lane >> 3) & 1) * 8;                     // + k0

    for (int kk = 0; kk < 16; kk++) {
        if (kk < 15) {
            int nb = lbase + (kk+1)*4;
            va0 = A4[nb]; va1 = A4[nb+1]; vb0 = B4[nb]; vb1 = B4[nb+1];
        }
        #pragma unroll
        for (int ks = 0; ks < 2; ks++) {
            int k0 = ks * 16;
            uint32_t a[2][4];
            #pragma unroll
            for (int mi = 0; mi < 2; mi++) {
                unsigned ad = (unsigned)__cvta_generic_to_shared(
                    smA + (arow + mi*16)*LDK + acol + k0);
                asm volatile("ldmatrix.sync.aligned.m8n8.x4.shared.b16 {%0,%1,%2,%3},[%4];"
                    : "=r"(a[mi][0]),"=r"(a[mi][1]),"=r"(a[mi][2]),"=r"(a[mi][3]) : "r"(ad));
            }
            uint32_t b[8][2];
            #pragma unroll
            for (int p = 0; p < 4; p++) {
                unsigned bad = (unsigned)__cvta_generic_to_shared(
                    smB + (brow + p*16)*LDK + bcol + k0);
                uint32_t r0, r1, r2, r3;
                asm volatile("ldmatrix.sync.aligned.m8n8.x4.shared.b16 {%0,%1,%2,%3},[%4];"
                    : "=r"(r0),"=r"(r1),"=r"(r2),"=r"(r3) : "r"(bad));
                b[2*p][0]=r0; b[2*p][1]=r1; b[2*p+1][0]=r2; b[2*p+1][1]=r3;
            }
            #pragma unroll
            for (int mi = 0; mi < 2; mi++)
                #pragma unroll
                for (int ni = 0; ni < 8; ni++)
                    asm volatile(
                        "mma.sync.aligned.m16n8k16.row.col.f32.bf16.bf16.f32 "
                        "{%0,%1,%2,%3},{%4,%5,%6,%7},{%8,%9},{%0,%1,%2,%3};"
                        : "+f"(acc[mi][ni][0]),"+f"(acc[mi][ni][1]),
                          "+f"(acc[mi][ni][2]),"+f"(acc[mi][ni][3])
                        : "r"(a[mi][0]),"r"(a[mi][1]),"r"(a[mi][2]),"r"(a[mi][3]),
                          "r"(b[ni][0]),"r"(b[ni][1]));
        }
        __syncthreads();
        if (kk < 15) {
            sA4[0]=va0; sA4[1]=va1; sB4[0]=vb0; sB4[1]=vb1;
            __syncthreads();
        }
    }

    // ---- epilogue: d2 = sqA + sqB - 2*dot, per-row top-16 across 2 half-passes ----
    int g = lane >> 2, tg = lane & 3;
    float bd2[16]; int bi2[16];
    #pragma unroll
    for (int q = 0; q < 16; q++) { bd2[q] = finf(); bi2[q] = 0; }

    #pragma unroll
    for (int pass = 0; pass < 2; pass++) {
        __syncthreads();
        if (wn == pass) {
            #pragma unroll
            for (int mi = 0; mi < 2; mi++)
                #pragma unroll
                for (int ni = 0; ni < 8; ni++) {
                    int r0 = wm*32 + mi*16 + g;
                    int c0 = ni*8 + tg*2;
                    smd[r0*65 + c0]       = acc[mi][ni][0];
                    smd[r0*65 + c0 + 1]   = acc[mi][ni][1];
                    smd[(r0+8)*65 + c0]     = acc[mi][ni][2];
                    smd[(r0+8)*65 + c0 + 1] = acc[mi][ni][3];
                }
        }
        __syncthreads();
        if (tid < 128) {
            int grow = mt*TIL + tid;
            float sr = sqAs[tid];
            for (int j = 0; j < 64; j++) {
                int lc = pass*64 + j;
                int gcol = nt*TIL + lc;
                float v = sr + sqBs[lc] - 2.0f * smd[tid*65 + j];
                if (gcol == grow) v = finf();
                if (v < bd2[15]) {
                    bd2[15] = v; bi2[15] = gcol;
                    #pragma unroll
                    for (int q = 15; q > 0; q--)
                        if (bd2[q] < bd2[q-1]) {
                            float td = bd2[q]; bd2[q] = bd2[q-1]; bd2[q-1] = td;
                            int   ti = bi2[q]; bi2[q] = bi2[q-1]; bi2[q-1] = ti;
                        }
                }
            }
        }
    }
    if (tid < 128) {
        long base = (((long)bz*NTILES + nt)*CAND_T)*NROWS + mt*TIL + tid;
        #pragma unroll
        for (int q = 0; q < 16; q++) {
            g_cd[base + (long)q*NROWS] = bd2[q];
            g_ci[base + (long)q*NROWS] = bi2[q];
        }
    }
}

// ---------------- 5. merge per-tile candidates -> global top-16 ----------------
__global__ void merge_kernel() {
    int rid = blockIdx.x * blockDim.x + threadIdx.x;   // 0..16383
    int bz = rid >> 13, rl = rid & 8191;
    float bd[16]; int bi[16];
    #pragma unroll
    for (int q = 0; q < 16; q++) { bd[q] = finf(); bi[q] = 0; }
    for (int t = 0; t < NTILES; t++) {
        long base = (((long)bz*NTILES + t)*CAND_T)*NROWS + rl;
        for (int q = 0; q < CAND_T; q++) {
            float v = g_cd[base + (long)q*NROWS];
            if (v >= bd[15]) break;                    // tile candidates are sorted
            int c = g_ci[base + (long)q*NROWS];
            bd[15] = v; bi[15] = c;
            #pragma unroll
            for (int qq = 15; qq > 0; qq--)
                if (bd[qq] < bd[qq-1]) {
                    float td = bd[qq]; bd[qq] = bd[qq-1]; bd[qq-1] = td;
                    int   ti = bi[qq]; bi[qq] = bi[qq-1]; bi[qq-1] = ti;
                }
        }
    }
    #pragma unroll
    for (int q = 0; q < 16; q++) g_topi[rid*16 + q] = bi[q];
}

// ---------------- 6. EXACT fp64 refine + adjacency scatter ----------------
// One warp per row. For the 16 merged candidates compute d2 exactly in fp64
// (dot, both sq-norms, assembly all double), then select top-8 with
// lowest-index tie-break (matches jax.lax.top_k). Removes all of OUR rounding
// noise from the ranking; only the reference's own fp32 noise remains.
__global__ void refine_kernel(const float* __restrict__ feats, float* __restrict__ adj) {
    int w = (blockIdx.x * blockDim.x + threadIdx.x) >> 5;   // row id 0..16383
    int lane = threadIdx.x & 31;
    int bz = w >> 13, rl = w & 8191;
    const float* fr = feats + (long)w*FDIM;
    float r[16];
    #pragma unroll
    for (int i = 0; i < 16; i++) r[i] = fr[lane + i*32];

    // row sq-norm in fp64
    double sqr = 0.0;
    #pragma unroll
    for (int i = 0; i < 16; i++) sqr += (double)r[i] * (double)r[i];
    #pragma unroll
    for (int o = 16; o; o >>= 1) sqr += __shfl_xor_sync(0xffffffffu, sqr, o);

    double myd2 = __longlong_as_double(0x7ff0000000000000ll);  // +inf
    int myidx = 0x7fffffff;

    #pragma unroll 1
    for (int c = 0; c < 16; c++) {
        int ci = g_topi[w*16 + c];
        const float* fc = feats + ((long)bz*NROWS + ci)*FDIM;
        double acc = 0.0;   // sq_c - 2*dot, fused per-element
        #pragma unroll
        for (int i = 0; i < 16; i++) {
            double fv = (double)fc[lane + i*32];
            acc = fma(fv - 2.0*(double)r[i], fv, acc);   // fv*fv - 2*r*fv (exact-ish fp64)
        }
        #pragma unroll
        for (int o = 16; o; o >>= 1) acc += __shfl_xor_sync(0xffffffffu, acc, o);
        double d2 = sqr + acc;
        if (lane == c) { myd2 = d2; myidx = ci; }
    }

    long adjbase = (long)bz * NROWS * NROWS;
    for (int k = 0; k < 8; k++) {
        double bd = myd2; int bi = myidx;
        #pragma unroll
        for (int o = 16; o; o >>= 1) {
            double od = __shfl_xor_sync(0xffffffffu, bd, o);
            int    oi = __shfl_xor_sync(0xffffffffu, bi, o);
            if (od < bd || (od == bd && oi < bi)) { bd = od; bi = oi; }
        }
        if (myidx == bi) {                       // winner removes itself (indices unique)
            myd2 = __longlong_as_double(0x7ff0000000000000ll);
            myidx = 0x7fffffff;
        }
        if (lane == k) {
            atomicAdd(adj + adjbase + (long)rl*NROWS + bi, 0.5f);
            atomicAdd(adj + adjbase + (long)bi*NROWS + rl, 0.5f);
        }
    }
}

// ---------------- launch ----------------
extern "C" void kernel_launch(void* const* d_in, const int* in_sizes, int n_in,
                              void* d_out, int out_size) {
    const float* img = (const float*)d_in[0];   // [2,1,256,256,64] fp32; d_in[1]=n (always 8)
    float* feats = (float*)d_out;                       // [2,8192,512]
    float* adj   = feats + FEATS_ELEMS;                 // [2,8192,8192]

    patch_kernel<<<4096, 256>>>(img, feats);            // 2*8192*64 threads
    sqnorm_kernel<<<2048, 256>>>(feats);                // 8 rows/block
    zero_kernel<<<16384, 256>>>((float4*)adj, ADJ_ELEMS/4);
    dim3 gg(NTILES, NTILES, NB);
    gemm_topk_kernel<<<gg, 256>>>();
    merge_kernel<<<64, 256>>>();
    refine_kernel<<<2048, 256>>>(feats, adj);
}

// round 3
// speedup vs baseline: 1.1450x; 1.1450x over previous
#include <cuda_runtime.h>
#include <cuda_bf16.h>
#include <cstdint>

#define NB 2
#define NROWS 8192
#define FDIM 512
#define TIL 128
#define NTILES 64      // 8192/128
#define CAND_H 12      // top-12 per 64-col half
#define CAND_T 24      // per tile per row (2 halves)
#define FEATS_ELEMS ((long)NB*NROWS*FDIM)          // 8388608
#define ADJ_ELEMS   ((long)NB*NROWS*NROWS)         // 134217728

// ---------------- scratch (device globals: allowed) ----------------
__device__ __align__(16) __nv_bfloat16 g_fb[NB*NROWS*FDIM];          // 16MB bf16 feats
__device__ float g_sq[NB*NROWS];                                     // row sq norms
__device__ float g_cd[(long)NB*NTILES*CAND_T*NROWS];                 // cand dists
__device__ int   g_ci[(long)NB*NTILES*CAND_T*NROWS];                 // cand idx
__device__ int   g_topi[NB*NROWS*16];                                // merged top-16 idx

__device__ __forceinline__ float finf() { return __int_as_float(0x7f800000); }

__device__ __forceinline__ void cpa16(unsigned d, const void* s) {
    asm volatile("cp.async.cg.shared.global [%0], [%1], 16;\n" :: "r"(d), "l"(s));
}

// ---------------- 1. patch extraction ----------------
__global__ void patch_kernel(const float* __restrict__ img, float* __restrict__ feats) {
    int idx = blockIdx.x * blockDim.x + threadIdx.x;   // < 2*8192*64
    int fc = idx & 63;
    int t  = idx >> 6;
    int p  = t & 8191;
    int b  = t >> 13;
    int ph = fc >> 3, pw = fc & 7;
    int db = p & 7, wb = (p >> 3) & 31, hb = p >> 8;
    const float4* src = (const float4*)(img + (long)b*4194304
                          + (long)(hb*8+ph)*16384 + (long)(wb*8+pw)*64 + db*8);
    float4 v0 = src[0], v1 = src[1];
    long o = (long)t*FDIM + fc*8;
    float4* dst = (float4*)(feats + o);
    dst[0] = v0; dst[1] = v1;
    __nv_bfloat162* bp = (__nv_bfloat162*)(g_fb + o);
    bp[0] = __floats2bfloat162_rn(v0.x, v0.y);
    bp[1] = __floats2bfloat162_rn(v0.z, v0.w);
    bp[2] = __floats2bfloat162_rn(v1.x, v1.y);
    bp[3] = __floats2bfloat162_rn(v1.z, v1.w);
}

// ---------------- 2. squared norms (one warp per row) ----------------
__global__ void sqnorm_kernel(const float* __restrict__ feats) {
    int row = blockIdx.x * 8 + (threadIdx.x >> 5);
    int lane = threadIdx.x & 31;
    const float4* f = (const float4*)(feats + (long)row*FDIM);
    float s = 0.f;
    #pragma unroll
    for (int i = 0; i < 4; i++) {
        float4 v = f[lane + i*32];
        s = fmaf(v.x,v.x, fmaf(v.y,v.y, fmaf(v.z,v.z, fmaf(v.w,v.w, s))));
    }
    #pragma unroll
    for (int o = 16; o; o >>= 1) s += __shfl_xor_sync(0xffffffffu, s, o);
    if (!lane) g_sq[row] = s;
}

// ---------------- 3. zero the adjacency region ----------------
__global__ void zero_kernel(float4* __restrict__ p, long n4) {
    long i = blockIdx.x * (long)blockDim.x + threadIdx.x;
    long stride = gridDim.x * (long)blockDim.x;
    float4 z = make_float4(0.f, 0.f, 0.f, 0.f);
    for (; i < n4; i += stride) p[i] = z;
}

// ---------------- 4. bf16 mma.sync GEMM (4-stage cp.async) + fused top-12x2 ----------------
// CTA 128x128 tile, K=512, BK=32, 256 threads (8 warps, warp tile 32m x 64n)
#define LDK 40                 // smem row stride in bf16 (80B, 16B aligned, conflict-free)
#define STAGE_B 20480          // bytes per stage (A 10240 + B 10240)
#define NSTAGE 4
#define DSMEM_BYTES (NSTAGE*STAGE_B)   // 81920 (>= 128*129*4 = 66048 epilogue)

__global__ __launch_bounds__(256) void gemm_topk_kernel() {
    extern __shared__ __align__(16) char dyn[];
    __shared__ float sqAs[128], sqBs[128];

    int nt = blockIdx.x, mt = blockIdx.y, bz = blockIdx.z;
    int tid = threadIdx.x;
    int lane = tid & 31, wid = tid >> 5;
    int wm = wid >> 1, wn = wid & 1;

    const __nv_bfloat16* Ag = g_fb + ((long)bz*NROWS + mt*TIL) * FDIM;
    const __nv_bfloat16* Bg = g_fb + ((long)bz*NROWS + nt*TIL) * FDIM;
    const uint4* A4 = (const uint4*)Ag;     // row = 64 uint4
    const uint4* B4 = (const uint4*)Bg;

    if (tid < 128) sqAs[tid] = g_sq[bz*NROWS + mt*TIL + tid];
    else           sqBs[tid-128] = g_sq[bz*NROWS + nt*TIL + (tid-128)];

    // per-thread copy mapping: chunks cid = tid and tid+256 (of 512) for each matrix
    int r0c = tid >> 2,         c0c = tid & 3;          // cid = tid
    int r1c = (tid + 256) >> 2, c1c = (tid + 256) & 3;  // cid = tid+256
    unsigned dynb = (unsigned)__cvta_generic_to_shared(dyn);
    // byte offsets inside a stage
    unsigned dA0 = r0c*80 + c0c*16, dA1 = r1c*80 + c1c*16;

    float acc[2][8][4];
    #pragma unroll
    for (int a = 0; a < 2; a++)
        #pragma unroll
        for (int b = 0; b < 8; b++)
            #pragma unroll
            for (int c = 0; c < 4; c++) acc[a][b][c] = 0.f;

    // ---- prologue: issue stages 0..2 ----
    #pragma unroll
    for (int s = 0; s < NSTAGE-1; s++) {
        unsigned sb = dynb + s*STAGE_B;
        cpa16(sb + dA0,         A4 + (r0c*64 + s*4 + c0c));
        cpa16(sb + dA1,         A4 + (r1c*64 + s*4 + c1c));
        cpa16(sb + 10240 + dA0, B4 + (r0c*64 + s*4 + c0c));
        cpa16(sb + 10240 + dA1, B4 + (r1c*64 + s*4 + c1c));
        asm volatile("cp.async.commit_group;\n" ::);
    }

    // ldmatrix address components
    int arow = wm*32 + (lane & 15);                       // + mi*16
    int acol = (lane >> 4) * 8;                           // + k0
    int brow = wn*64 + (lane & 7) + (lane >> 4) * 8;      // + p*16
    int bcol = ((lane >> 3) & 1) * 8;                     // + k0

    #pragma unroll 4
    for (int kk = 0; kk < 16; kk++) {
        asm volatile("cp.async.wait_group 2;\n" ::);
        __syncthreads();
        int slot = kk & (NSTAGE-1);
        __nv_bfloat16* smA = (__nv_bfloat16*)(dyn + slot*STAGE_B);
        __nv_bfloat16* smB = (__nv_bfloat16*)(dyn + slot*STAGE_B + 10240);

        #pragma unroll
        for (int ks = 0; ks < 2; ks++) {
            int k0 = ks * 16;
            uint32_t a[2][4];
            #pragma unroll
            for (int mi = 0; mi < 2; mi++) {
                unsigned ad = (unsigned)__cvta_generic_to_shared(
                    smA + (arow + mi*16)*LDK + acol + k0);
                asm volatile("ldmatrix.sync.aligned.m8n8.x4.shared.b16 {%0,%1,%2,%3},[%4];"
                    : "=r"(a[mi][0]),"=r"(a[mi][1]),"=r"(a[mi][2]),"=r"(a[mi][3]) : "r"(ad));
            }
            uint32_t b[8][2];
            #pragma unroll
            for (int p = 0; p < 4; p++) {
                unsigned bad = (unsigned)__cvta_generic_to_shared(
                    smB + (brow + p*16)*LDK + bcol + k0);
                uint32_t r0, r1, r2, r3;
                asm volatile("ldmatrix.sync.aligned.m8n8.x4.shared.b16 {%0,%1,%2,%3},[%4];"
                    : "=r"(r0),"=r"(r1),"=r"(r2),"=r"(r3) : "r"(bad));
                b[2*p][0]=r0; b[2*p][1]=r1; b[2*p+1][0]=r2; b[2*p+1][1]=r3;
            }
            #pragma unroll
            for (int mi = 0; mi < 2; mi++)
                #pragma unroll
                for (int ni = 0; ni < 8; ni++)
                    asm volatile(
                        "mma.sync.aligned.m16n8k16.row.col.f32.bf16.bf16.f32 "
                        "{%0,%1,%2,%3},{%4,%5,%6,%7},{%8,%9},{%0,%1,%2,%3};"
                        : "+f"(acc[mi][ni][0]),"+f"(acc[mi][ni][1]),
                          "+f"(acc[mi][ni][2]),"+f"(acc[mi][ni][3])
                        : "r"(a[mi][0]),"r"(a[mi][1]),"r"(a[mi][2]),"r"(a[mi][3]),
                          "r"(b[ni][0]),"r"(b[ni][1]));
        }
        // issue stage kk+3 into the slot consumed at iter kk-1 (safe: sync above)
        if (kk < 13) {
            int s = kk + 3;
            unsigned sb = dynb + (s & (NSTAGE-1))*STAGE_B;
            cpa16(sb + dA0,         A4 + (r0c*64 + s*4 + c0c));
            cpa16(sb + dA1,         A4 + (r1c*64 + s*4 + c1c));
            cpa16(sb + 10240 + dA0, B4 + (r0c*64 + s*4 + c0c));
            cpa16(sb + 10240 + dA1, B4 + (r1c*64 + s*4 + c1c));
        }
        asm volatile("cp.async.commit_group;\n" ::);
    }

    // ---- epilogue: full 128x129 d2 tile, 256 threads, top-12 per 64-col half ----
    __syncthreads();
    float* smd = (float*)dyn;                 // 128 x 129 fp32 (aliases stages)
    {
        int g = lane >> 2, tg = lane & 3;
        #pragma unroll
        for (int mi = 0; mi < 2; mi++)
            #pragma unroll
            for (int ni = 0; ni < 8; ni++) {
                int r0 = wm*32 + mi*16 + g;
                int c0 = wn*64 + ni*8 + tg*2;
                smd[r0*129 + c0]       = acc[mi][ni][0];
                smd[r0*129 + c0 + 1]   = acc[mi][ni][1];
                smd[(r0+8)*129 + c0]     = acc[mi][ni][2];
                smd[(r0+8)*129 + c0 + 1] = acc[mi][ni][3];
            }
    }
    __syncthreads();

    {
        int row = tid & 127, half = tid >> 7;
        int grow = mt*TIL + row;
        float sr = sqAs[row];
        float bd[CAND_H]; int bi[CAND_H];
        #pragma unroll
        for (int q = 0; q < CAND_H; q++) { bd[q] = finf(); bi[q] = 0; }
        const float* rowp = smd + row*129 + half*64;
        int gc0 = nt*TIL + half*64;
        #pragma unroll 4
        for (int j = 0; j < 64; j++) {
            int gcol = gc0 + j;
            float v = sr + sqBs[half*64 + j] - 2.0f * rowp[j];
            if (gcol == grow) v = finf();
            if (v < bd[CAND_H-1]) {
                bd[CAND_H-1] = v; bi[CAND_H-1] = gcol;
                #pragma unroll
                for (int q = CAND_H-1; q > 0; q--)
                    if (bd[q] < bd[q-1]) {
                        float td = bd[q]; bd[q] = bd[q-1]; bd[q-1] = td;
                        int   ti = bi[q]; bi[q] = bi[q-1]; bi[q-1] = ti;
                    }
            }
        }
        long base = (((long)bz*NTILES + nt)*CAND_T + half*CAND_H)*NROWS + mt*TIL + row;
        #pragma unroll
        for (int q = 0; q < CAND_H; q++) {
            g_cd[base + (long)q*NROWS] = bd[q];
            g_ci[base + (long)q*NROWS] = bi[q];
        }
    }
}

// ---------------- 5. merge per-tile candidates -> global top-16 ----------------
__global__ void merge_kernel() {
    int rid = blockIdx.x * blockDim.x + threadIdx.x;   // 0..16383
    int bz = rid >> 13, rl = rid & 8191;
    float bd[16]; int bi[16];
    #pragma unroll
    for (int q = 0; q < 16; q++) { bd[q] = finf(); bi[q] = 0; }
    for (int t = 0; t < NTILES; t++) {
        long tb = ((long)bz*NTILES + t)*CAND_T*NROWS + rl;
        #pragma unroll
        for (int h = 0; h < 2; h++) {
            long base = tb + (long)h*CAND_H*NROWS;
            for (int q = 0; q < CAND_H; q++) {
                float v = g_cd[base + (long)q*NROWS];
                if (v >= bd[15]) break;                // run is sorted ascending
                int c = g_ci[base + (long)q*NROWS];
                bd[15] = v; bi[15] = c;
                #pragma unroll
                for (int qq = 15; qq > 0; qq--)
                    if (bd[qq] < bd[qq-1]) {
                        float td = bd[qq]; bd[qq] = bd[qq-1]; bd[qq-1] = td;
                        int   ti = bi[qq]; bi[qq] = bi[qq-1]; bi[qq-1] = ti;
                    }
            }
        }
    }
    #pragma unroll
    for (int q = 0; q < 16; q++) g_topi[rid*16 + q] = bi[q];
}

// ---------------- 6. EXACT fp64 refine + adjacency scatter ----------------
__global__ void refine_kernel(const float* __restrict__ feats, float* __restrict__ adj) {
    int w = (blockIdx.x * blockDim.x + threadIdx.x) >> 5;   // row id 0..16383
    int lane = threadIdx.x & 31;
    int bz = w >> 13, rl = w & 8191;
    const float* fr = feats + (long)w*FDIM;
    float r[16];
    #pragma unroll
    for (int i = 0; i < 16; i++) r[i] = fr[lane + i*32];

    double sqr = 0.0;
    #pragma unroll
    for (int i = 0; i < 16; i++) sqr += (double)r[i] * (double)r[i];
    #pragma unroll
    for (int o = 16; o; o >>= 1) sqr += __shfl_xor_sync(0xffffffffu, sqr, o);

    double myd2 = __longlong_as_double(0x7ff0000000000000ll);  // +inf
    int myidx = 0x7fffffff;

    #pragma unroll 1
    for (int c = 0; c < 16; c++) {
        int ci = g_topi[w*16 + c];
        const float* fc = feats + ((long)bz*NROWS + ci)*FDIM;
        double acc = 0.0;   // sq_c - 2*dot fused
        #pragma unroll
        for (int i = 0; i < 16; i++) {
            double fv = (double)fc[lane + i*32];
            acc = fma(fv - 2.0*(double)r[i], fv, acc);
        }
        #pragma unroll
        for (int o = 16; o; o >>= 1) acc += __shfl_xor_sync(0xffffffffu, acc, o);
        double d2 = sqr + acc;
        if (lane == c) { myd2 = d2; myidx = ci; }
    }

    long adjbase = (long)bz * NROWS * NROWS;
    for (int k = 0; k < 8; k++) {
        double bdv = myd2; int biv = myidx;
        #pragma unroll
        for (int o = 16; o; o >>= 1) {
            double od = __shfl_xor_sync(0xffffffffu, bdv, o);
            int    oi = __shfl_xor_sync(0xffffffffu, biv, o);
            if (od < bdv || (od == bdv && oi < biv)) { bdv = od; biv = oi; }
        }
        if (myidx == biv) {
            myd2 = __longlong_as_double(0x7ff0000000000000ll);
            myidx = 0x7fffffff;
        }
        if (lane == k) {
            atomicAdd(adj + adjbase + (long)rl*NROWS + biv, 0.5f);
            atomicAdd(adj + adjbase + (long)biv*NROWS + rl, 0.5f);
        }
    }
}

// ---------------- launch ----------------
extern "C" void kernel_launch(void* const* d_in, const int* in_sizes, int n_in,
                              void* d_out, int out_size) {
    const float* img = (const float*)d_in[0];   // [2,1,256,256,64] fp32; d_in[1]=n (8)
    float* feats = (float*)d_out;                       // [2,8192,512]
    float* adj   = feats + FEATS_ELEMS;                 // [2,8192,8192]

    cudaFuncSetAttribute(gemm_topk_kernel,
                         cudaFuncAttributeMaxDynamicSharedMemorySize, DSMEM_BYTES);

    patch_kernel<<<4096, 256>>>(img, feats);
    sqnorm_kernel<<<2048, 256>>>(feats);
    zero_kernel<<<16384, 256>>>((float4*)adj, ADJ_ELEMS/4);
    dim3 gg(NTILES, NTILES, NB);
    gemm_topk_kernel<<<gg, 256, DSMEM_BYTES>>>();
    merge_kernel<<<64, 256>>>();
    refine_kernel<<<2048, 256>>>(feats, adj);
}

// round 4
// speedup vs baseline: 2.4155x; 2.1096x over previous
#include <cuda_runtime.h>
#include <cuda_bf16.h>
#include <cstdint>

#define NB 2
#define NROWS 8192
#define FDIM 512
#define TIL 128
#define NTILES 64      // 8192/128
#define CAND_H 12      // top-12 per 64-col half
#define CAND_T 24      // per slot per row (2 halves)
#define NUTRI 2080     // 64*65/2 upper-triangular tiles
#define FEATS_ELEMS ((long)NB*NROWS*FDIM)          // 8388608
#define ADJ_ELEMS   ((long)NB*NROWS*NROWS)         // 134217728

// ---------------- scratch (device globals: allowed) ----------------
__device__ __align__(16) __nv_bfloat16 g_fb[NB*NROWS*FDIM];          // 16MB bf16 feats
__device__ float  g_sq[NB*NROWS];                                    // fp32 sq norms (gemm)
__device__ double g_sqd[NB*NROWS];                                   // exact sq norms (refine)
__device__ float g_cd2[(long)NB*NROWS*NTILES*CAND_T];                // 100MB cand dists [row][slot][q]
__device__ int   g_ci2[(long)NB*NROWS*NTILES*CAND_T];                // 100MB cand idx

__device__ __forceinline__ float finf() { return __int_as_float(0x7f800000); }

__device__ __forceinline__ void cpa16(unsigned d, const void* s) {
    asm volatile("cp.async.cg.shared.global [%0], [%1], 16;\n" :: "r"(d), "l"(s));
}

// df64 helpers — rounding-mode intrinsics so fast-math can't fold them
__device__ __forceinline__ void df_acc(float& hi, float& lo, float p) {
    float s  = __fadd_rn(hi, p);
    float t  = __fsub_rn(s, hi);
    float er = __fadd_rn(__fsub_rn(hi, __fsub_rn(s, t)), __fsub_rn(p, t));
    hi = s; lo = __fadd_rn(lo, er);
}
__device__ __forceinline__ void df_prod_acc(float& hi, float& lo, float a, float b) {
    float p = __fmul_rn(a, b);
    float e = __fmaf_rn(a, b, -p);
    df_acc(hi, lo, p);
    lo = __fadd_rn(lo, e);
}
__device__ __forceinline__ void df_join(float& hi, float& lo, float oh, float ol) {
    float s  = __fadd_rn(hi, oh);
    float t  = __fsub_rn(s, hi);
    float er = __fadd_rn(__fsub_rn(hi, __fsub_rn(s, t)), __fsub_rn(oh, t));
    hi = s; lo = __fadd_rn(lo, __fadd_rn(ol, er));
}

// ---------------- 1. patch extraction + fused exact sqnorm ----------------
__global__ void patch_kernel(const float* __restrict__ img, float* __restrict__ feats) {
    __shared__ float sh_h[8], sh_l[8];
    int idx = blockIdx.x * blockDim.x + threadIdx.x;   // < 2*8192*64
    int tid = threadIdx.x, lane = tid & 31;
    int fc = idx & 63;
    int t  = idx >> 6;
    int p  = t & 8191;
    int b  = t >> 13;
    int ph = fc >> 3, pw = fc & 7;
    int db = p & 7, wb = (p >> 3) & 31, hb = p >> 8;
    const float4* src = (const float4*)(img + (long)b*4194304
                          + (long)(hb*8+ph)*16384 + (long)(wb*8+pw)*64 + db*8);
    float4 v0 = src[0], v1 = src[1];
    long o = (long)t*FDIM + fc*8;
    float4* dst = (float4*)(feats + o);
    dst[0] = v0; dst[1] = v1;
    __nv_bfloat162* bp = (__nv_bfloat162*)(g_fb + o);
    bp[0] = __floats2bfloat162_rn(v0.x, v0.y);
    bp[1] = __floats2bfloat162_rn(v0.z, v0.w);
    bp[2] = __floats2bfloat162_rn(v1.x, v1.y);
    bp[3] = __floats2bfloat162_rn(v1.z, v1.w);

    // df64 partial sq-norm over this thread's 8 values
    float hi = 0.f, lo = 0.f;
    df_prod_acc(hi, lo, v0.x, v0.x); df_prod_acc(hi, lo, v0.y, v0.y);
    df_prod_acc(hi, lo, v0.z, v0.z); df_prod_acc(hi, lo, v0.w, v0.w);
    df_prod_acc(hi, lo, v1.x, v1.x); df_prod_acc(hi, lo, v1.y, v1.y);
    df_prod_acc(hi, lo, v1.z, v1.z); df_prod_acc(hi, lo, v1.w, v1.w);
    #pragma unroll
    for (int ofs = 16; ofs; ofs >>= 1) {
        float oh = __shfl_xor_sync(0xffffffffu, hi, ofs);
        float ol = __shfl_xor_sync(0xffffffffu, lo, ofs);
        df_join(hi, lo, oh, ol);
    }
    int w = tid >> 5;
    if (!lane) { sh_h[w] = hi; sh_l[w] = lo; }
    __syncthreads();
    if (tid < 4) {                 // 4 rows per block, 2 warps each
        float h1 = sh_h[tid*2], l1 = sh_l[tid*2];
        float h2 = sh_h[tid*2+1], l2 = sh_l[tid*2+1];
        df_join(h1, l1, h2, l2);
        double d = (double)h1 + (double)l1;
        int row = blockIdx.x*4 + tid;
        g_sqd[row] = d;
        g_sq[row]  = (float)d;
    }
}

// ---------------- 2. zero the adjacency region ----------------
__global__ void zero_kernel(float4* __restrict__ p, long n4) {
    long i = blockIdx.x * (long)blockDim.x + threadIdx.x;
    long stride = gridDim.x * (long)blockDim.x;
    float4 z = make_float4(0.f, 0.f, 0.f, 0.f);
    for (; i < n4; i += stride) p[i] = z;
}

// ---------------- 3. symmetric bf16 GEMM (4-stage cp.async) + dual-direction top-12 ----------------
#define LDK 40                 // smem row stride in bf16 (80B, 16B aligned, conflict-free)
#define STAGE_B 20480          // bytes per stage (A 10240 + B 10240)
#define NSTAGE 4
#define DSMEM_BYTES (NSTAGE*STAGE_B)   // 81920 (>= 128*129*4 = 66048 epilogue)

__global__ __launch_bounds__(256) void gemm_topk_kernel() {
    extern __shared__ __align__(16) char dyn[];
    __shared__ float sqAs[128], sqBs[128];

    // decode upper-triangular tile (mt, nt), nt >= mt
    int u = blockIdx.x, bz = blockIdx.z;
    int mt = (int)floorf(64.5f - sqrtf(64.5f*64.5f - 2.0f*(float)u));
    while ((mt+1)*(129-(mt+1))/2 <= u) mt++;
    while (mt*(129-mt)/2 > u) mt--;
    int nt = mt + (u - mt*(129-mt)/2);

    int tid = threadIdx.x;
    int lane = tid & 31, wid = tid >> 5;
    int wm = wid >> 1, wn = wid & 1;

    const __nv_bfloat16* Ag = g_fb + ((long)bz*NROWS + mt*TIL) * FDIM;
    const __nv_bfloat16* Bg = g_fb + ((long)bz*NROWS + nt*TIL) * FDIM;
    const uint4* A4 = (const uint4*)Ag;     // row = 64 uint4
    const uint4* B4 = (const uint4*)Bg;

    if (tid < 128) sqAs[tid] = g_sq[bz*NROWS + mt*TIL + tid];
    else           sqBs[tid-128] = g_sq[bz*NROWS + nt*TIL + (tid-128)];

    int r0c = tid >> 2,         c0c = tid & 3;
    int r1c = (tid + 256) >> 2, c1c = (tid + 256) & 3;
    unsigned dynb = (unsigned)__cvta_generic_to_shared(dyn);
    unsigned dA0 = r0c*80 + c0c*16, dA1 = r1c*80 + c1c*16;

    float acc[2][8][4];
    #pragma unroll
    for (int a = 0; a < 2; a++)
        #pragma unroll
        for (int b = 0; b < 8; b++)
            #pragma unroll
            for (int c = 0; c < 4; c++) acc[a][b][c] = 0.f;

    #pragma unroll
    for (int s = 0; s < NSTAGE-1; s++) {
        unsigned sb = dynb + s*STAGE_B;
        cpa16(sb + dA0,         A4 + (r0c*64 + s*4 + c0c));
        cpa16(sb + dA1,         A4 + (r1c*64 + s*4 + c1c));
        cpa16(sb + 10240 + dA0, B4 + (r0c*64 + s*4 + c0c));
        cpa16(sb + 10240 + dA1, B4 + (r1c*64 + s*4 + c1c));
        asm volatile("cp.async.commit_group;\n" ::);
    }

    int arow = wm*32 + (lane & 15);
    int acol = (lane >> 4) * 8;
    int brow = wn*64 + (lane & 7) + (lane >> 4) * 8;
    int bcol = ((lane >> 3) & 1) * 8;

    #pragma unroll 4
    for (int kk = 0; kk < 16; kk++) {
        asm volatile("cp.async.wait_group 2;\n" ::);
        __syncthreads();
        int slot = kk & (NSTAGE-1);
        __nv_bfloat16* smA = (__nv_bfloat16*)(dyn + slot*STAGE_B);
        __nv_bfloat16* smB = (__nv_bfloat16*)(dyn + slot*STAGE_B + 10240);

        #pragma unroll
        for (int ks = 0; ks < 2; ks++) {
            int k0 = ks * 16;
            uint32_t a[2][4];
            #pragma unroll
            for (int mi = 0; mi < 2; mi++) {
                unsigned ad = (unsigned)__cvta_generic_to_shared(
                    smA + (arow + mi*16)*LDK + acol + k0);
                asm volatile("ldmatrix.sync.aligned.m8n8.x4.shared.b16 {%0,%1,%2,%3},[%4];"
                    : "=r"(a[mi][0]),"=r"(a[mi][1]),"=r"(a[mi][2]),"=r"(a[mi][3]) : "r"(ad));
            }
            uint32_t b[8][2];
            #pragma unroll
            for (int p = 0; p < 4; p++) {
                unsigned bad = (unsigned)__cvta_generic_to_shared(
                    smB + (brow + p*16)*LDK + bcol + k0);
                uint32_t r0, r1, r2, r3;
                asm volatile("ldmatrix.sync.aligned.m8n8.x4.shared.b16 {%0,%1,%2,%3},[%4];"
                    : "=r"(r0),"=r"(r1),"=r"(r2),"=r"(r3) : "r"(bad));
                b[2*p][0]=r0; b[2*p][1]=r1; b[2*p+1][0]=r2; b[2*p+1][1]=r3;
            }
            #pragma unroll
            for (int mi = 0; mi < 2; mi++)
                #pragma unroll
                for (int ni = 0; ni < 8; ni++)
                    asm volatile(
                        "mma.sync.aligned.m16n8k16.row.col.f32.bf16.bf16.f32 "
                        "{%0,%1,%2,%3},{%4,%5,%6,%7},{%8,%9},{%0,%1,%2,%3};"
                        : "+f"(acc[mi][ni][0]),"+f"(acc[mi][ni][1]),
                          "+f"(acc[mi][ni][2]),"+f"(acc[mi][ni][3])
                        : "r"(a[mi][0]),"r"(a[mi][1]),"r"(a[mi][2]),"r"(a[mi][3]),
                          "r"(b[ni][0]),"r"(b[ni][1]));
        }
        if (kk < 13) {
            int s = kk + 3;
            unsigned sb = dynb + (s & (NSTAGE-1))*STAGE_B;
            cpa16(sb + dA0,         A4 + (r0c*64 + s*4 + c0c));
            cpa16(sb + dA1,         A4 + (r1c*64 + s*4 + c1c));
            cpa16(sb + 10240 + dA0, B4 + (r0c*64 + s*4 + c0c));
            cpa16(sb + 10240 + dA1, B4 + (r1c*64 + s*4 + c1c));
        }
        asm volatile("cp.async.commit_group;\n" ::);
    }

    // ---- epilogue: write full 128x129 d2 tile, then row-scan + (off-diag) col-scan ----
    __syncthreads();
    float* smd = (float*)dyn;                 // 128 x 129 fp32 (aliases stages)
    {
        int g = lane >> 2, tg = lane & 3;
        #pragma unroll
        for (int mi = 0; mi < 2; mi++)
            #pragma unroll
            for (int ni = 0; ni < 8; ni++) {
                int r0 = wm*32 + mi*16 + g;
                int c0 = wn*64 + ni*8 + tg*2;
                smd[r0*129 + c0]       = acc[mi][ni][0];
                smd[r0*129 + c0 + 1]   = acc[mi][ni][1];
                smd[(r0+8)*129 + c0]     = acc[mi][ni][2];
                smd[(r0+8)*129 + c0 + 1] = acc[mi][ni][3];
            }
    }
    __syncthreads();

    int rc = tid & 127, half = tid >> 7;
    {   // row-scan: candidates for rows of block mt, neighbors in block nt
        int grow = mt*TIL + rc;
        float sr = sqAs[rc];
        float bd[CAND_H]; int bi[CAND_H];
        #pragma unroll
        for (int q = 0; q < CAND_H; q++) { bd[q] = finf(); bi[q] = 0; }
        const float* rowp = smd + rc*129 + half*64;
        int gc0 = nt*TIL + half*64;
        #pragma unroll 4
        for (int j = 0; j < 64; j++) {
            int gcol = gc0 + j;
            float v = sr + sqBs[half*64 + j] - 2.0f * rowp[j];
            if (gcol == grow) v = finf();
            if (v < bd[CAND_H-1]) {
                bd[CAND_H-1] = v; bi[CAND_H-1] = gcol;
                #pragma unroll
                for (int q = CAND_H-1; q > 0; q--)
                    if (bd[q] < bd[q-1]) {
                        float td = bd[q]; bd[q] = bd[q-1]; bd[q-1] = td;
                        int   ti = bi[q]; bi[q] = bi[q-1]; bi[q-1] = ti;
                    }
            }
        }
        long base = (((long)(bz*NROWS + grow))*NTILES + nt)*CAND_T + half*CAND_H;
        #pragma unroll
        for (int q = 0; q < CAND_H; q++) { g_cd2[base+q] = bd[q]; g_ci2[base+q] = bi[q]; }
    }
    if (nt != mt) {  // col-scan: candidates for rows of block nt, neighbors in block mt
        float sc = sqBs[rc];
        float bd[CAND_H]; int bi[CAND_H];
        #pragma unroll
        for (int q = 0; q < CAND_H; q++) { bd[q] = finf(); bi[q] = 0; }
        #pragma unroll 4
        for (int j = 0; j < 64; j++) {
            int r = half*64 + j;
            float v = sqAs[r] + sc - 2.0f * smd[r*129 + rc];
            if (v < bd[CAND_H-1]) {
                bd[CAND_H-1] = v; bi[CAND_H-1] = mt*TIL + r;
                #pragma unroll
                for (int q = CAND_H-1; q > 0; q--)
                    if (bd[q] < bd[q-1]) {
                        float td = bd[q]; bd[q] = bd[q-1]; bd[q-1] = td;
                        int   ti = bi[q]; bi[q] = bi[q-1]; bi[q-1] = ti;
                    }
            }
        }
        long base = (((long)(bz*NROWS + nt*TIL + rc))*NTILES + mt)*CAND_T + half*CAND_H;
        #pragma unroll
        for (int q = 0; q < CAND_H; q++) { g_cd2[base+q] = bd[q]; g_ci2[base+q] = bi[q]; }
    }
}

// ---------------- 4. fused merge (warp/row) + df64 refine + scatter ----------------
__global__ __launch_bounds__(256) void merge_refine_kernel(
        const float* __restrict__ feats, float* __restrict__ adj) {
    int gw = (blockIdx.x * blockDim.x + threadIdx.x) >> 5;   // row id 0..16383
    int lane = threadIdx.x & 31;
    int bz = gw >> 13, rl = gw & 8191;

    // ---- lane-local top-16 over 2 slots (4 sorted runs of 12) ----
    float bd[16]; int bi[16];
    #pragma unroll
    for (int q = 0; q < 16; q++) { bd[q] = finf(); bi[q] = 0x7fffffff; }
    long rb = (long)gw * NTILES * CAND_T;
    #pragma unroll 1
    for (int ss = 0; ss < 2; ss++) {
        long sb = rb + (long)(lane*2 + ss) * CAND_T;
        #pragma unroll
        for (int h = 0; h < 2; h++) {
            long base = sb + h*CAND_H;
            #pragma unroll 1
            for (int q = 0; q < CAND_H; q++) {
                float v = g_cd2[base+q];
                if (v >= bd[15]) break;          // run sorted ascending
                int c = g_ci2[base+q];
                bd[15] = v; bi[15] = c;
                #pragma unroll
                for (int qq = 15; qq > 0; qq--)
                    if (bd[qq] < bd[qq-1]) {
                        float td = bd[qq]; bd[qq] = bd[qq-1]; bd[qq-1] = td;
                        int   ti = bi[qq]; bi[qq] = bi[qq-1]; bi[qq-1] = ti;
                    }
            }
        }
    }

    // ---- warp head-merge: global top-16, candidate k lands in lane k ----
    int myci = 0;
    #pragma unroll 1
    for (int k = 0; k < 16; k++) {
        float v = bd[0]; int ix = bi[0];
        #pragma unroll
        for (int o = 16; o; o >>= 1) {
            float ov = __shfl_xor_sync(0xffffffffu, v, o);
            int   oi = __shfl_xor_sync(0xffffffffu, ix, o);
            if (ov < v || (ov == v && oi < ix)) { v = ov; ix = oi; }
        }
        if (lane == k) myci = ix;
        if (bd[0] == v && bi[0] == ix) {         // unique winner pops its head
            #pragma unroll
            for (int q = 0; q < 15; q++) { bd[q] = bd[q+1]; bi[q] = bi[q+1]; }
            bd[15] = finf(); bi[15] = 0x7fffffff;
        }
    }

    // ---- df64 exact refine of the 16 candidates ----
    const float* fr = feats + (long)gw*FDIM;
    float r[16];
    #pragma unroll
    for (int i = 0; i < 16; i++) r[i] = fr[lane + i*32];
    double sqr = g_sqd[gw];

    double myd2 = __longlong_as_double(0x7ff0000000000000ll);
    int myidx = 0x7fffffff;

    #pragma unroll 2
    for (int c = 0; c < 16; c++) {
        int ci = __shfl_sync(0xffffffffu, myci, c);
        const float* fc = feats + ((long)bz*NROWS + ci)*FDIM;
        float hi = 0.f, lo = 0.f;
        #pragma unroll
        for (int i = 0; i < 16; i++)
            df_prod_acc(hi, lo, r[i], fc[lane + i*32]);
        #pragma unroll
        for (int o = 16; o; o >>= 1) {
            float oh = __shfl_xor_sync(0xffffffffu, hi, o);
            float ol = __shfl_xor_sync(0xffffffffu, lo, o);
            df_join(hi, lo, oh, ol);
        }
        double dot = (double)hi + (double)lo;
        double d2 = sqr + g_sqd[bz*NROWS + ci] - 2.0*dot;
        if (lane == c) { myd2 = d2; myidx = ci; }
    }

    // ---- top-8 select (idx tiebreak) + symmetric scatter ----
    long adjbase = (long)bz * NROWS * NROWS;
    #pragma unroll 1
    for (int k = 0; k < 8; k++) {
        double bdv = myd2; int biv = myidx;
        #pragma unroll
        for (int o = 16; o; o >>= 1) {
            double od = __shfl_xor_sync(0xffffffffu, bdv, o);
            int    oi = __shfl_xor_sync(0xffffffffu, biv, o);
            if (od < bdv || (od == bdv && oi < biv)) { bdv = od; biv = oi; }
        }
        if (myidx == biv) {
            myd2 = __longlong_as_double(0x7ff0000000000000ll);
            myidx = 0x7fffffff;
        }
        if (lane == k) {
            atomicAdd(adj + adjbase + (long)rl*NROWS + biv, 0.5f);
            atomicAdd(adj + adjbase + (long)biv*NROWS + rl, 0.5f);
        }
    }
}

// ---------------- launch ----------------
extern "C" void kernel_launch(void* const* d_in, const int* in_sizes, int n_in,
                              void* d_out, int out_size) {
    const float* img = (const float*)d_in[0];   // [2,1,256,256,64] fp32; d_in[1]=n (8)
    float* feats = (float*)d_out;                       // [2,8192,512]
    float* adj   = feats + FEATS_ELEMS;                 // [2,8192,8192]

    cudaFuncSetAttribute(gemm_topk_kernel,
                         cudaFuncAttributeMaxDynamicSharedMemorySize, DSMEM_BYTES);

    patch_kernel<<<4096, 256>>>(img, feats);
    zero_kernel<<<16384, 256>>>((float4*)adj, ADJ_ELEMS/4);
    dim3 gg(NUTRI, 1, NB);
    gemm_topk_kernel<<<gg, 256, DSMEM_BYTES>>>();
    merge_refine_kernel<<<2048, 256>>>(feats, adj);
}

// round 5
// speedup vs baseline: 2.8008x; 1.1595x over previous
#include <cuda_runtime.h>
#include <cuda_bf16.h>
#include <cstdint>

#define NB 2
#define NROWS 8192
#define FDIM 512
#define TIL 128
#define NTILES 64      // 8192/128
#define CAND_K 12      // top-12 per 128-col tile
#define NUTRI 2080     // 64*65/2 upper-triangular tiles
#define FEATS_ELEMS ((long)NB*NROWS*FDIM)          // 8388608
#define ADJ_ELEMS   ((long)NB*NROWS*NROWS)         // 134217728

// ---------------- scratch (device globals: allowed) ----------------
__device__ __align__(16) __nv_bfloat16 g_fb[NB*NROWS*FDIM];          // 16MB bf16 feats
__device__ float  g_sq[NB*NROWS];                                    // fp32 sq norms
__device__ double g_sqd[NB*NROWS];                                   // exact sq norms (refine)
__device__ unsigned long long g_ck[(long)NB*NROWS*NTILES*CAND_K];    // 100MB packed cand

__device__ __forceinline__ float finf() { return __int_as_float(0x7f800000); }

__device__ __forceinline__ void cpa16(unsigned d, const void* s) {
    asm volatile("cp.async.cg.shared.global [%0], [%1], 16;\n" :: "r"(d), "l"(s));
}

__device__ __forceinline__ unsigned long long packkey(float k, int col) {
    unsigned u = __float_as_uint(k);
    u ^= (unsigned)((int)u >> 31) | 0x80000000u;   // orderable-uint transform
    return ((unsigned long long)u << 13) | (unsigned)col;
}

// df64 helpers — rounding-mode intrinsics so fast-math can't fold them
__device__ __forceinline__ void df_acc(float& hi, float& lo, float p) {
    float s  = __fadd_rn(hi, p);
    float t  = __fsub_rn(s, hi);
    float er = __fadd_rn(__fsub_rn(hi, __fsub_rn(s, t)), __fsub_rn(p, t));
    hi = s; lo = __fadd_rn(lo, er);
}
__device__ __forceinline__ void df_prod_acc(float& hi, float& lo, float a, float b) {
    float p = __fmul_rn(a, b);
    float e = __fmaf_rn(a, b, -p);
    df_acc(hi, lo, p);
    lo = __fadd_rn(lo, e);
}
__device__ __forceinline__ void df_join(float& hi, float& lo, float oh, float ol) {
    float s  = __fadd_rn(hi, oh);
    float t  = __fsub_rn(s, hi);
    float er = __fadd_rn(__fsub_rn(hi, __fsub_rn(s, t)), __fsub_rn(oh, t));
    hi = s; lo = __fadd_rn(lo, __fadd_rn(ol, er));
}

// ---------------- 1. patch extraction + fused exact sqnorm ----------------
__global__ void patch_kernel(const float* __restrict__ img, float* __restrict__ feats) {
    __shared__ float sh_h[8], sh_l[8];
    int idx = blockIdx.x * blockDim.x + threadIdx.x;   // < 2*8192*64
    int tid = threadIdx.x, lane = tid & 31;
    int fc = idx & 63;
    int t  = idx >> 6;
    int p  = t & 8191;
    int b  = t >> 13;
    int ph = fc >> 3, pw = fc & 7;
    int db = p & 7, wb = (p >> 3) & 31, hb = p >> 8;
    const float4* src = (const float4*)(img + (long)b*4194304
                          + (long)(hb*8+ph)*16384 + (long)(wb*8+pw)*64 + db*8);
    float4 v0 = src[0], v1 = src[1];
    long o = (long)t*FDIM + fc*8;
    float4* dst = (float4*)(feats + o);
    dst[0] = v0; dst[1] = v1;
    __nv_bfloat162* bp = (__nv_bfloat162*)(g_fb + o);
    bp[0] = __floats2bfloat162_rn(v0.x, v0.y);
    bp[1] = __floats2bfloat162_rn(v0.z, v0.w);
    bp[2] = __floats2bfloat162_rn(v1.x, v1.y);
    bp[3] = __floats2bfloat162_rn(v1.z, v1.w);

    float hi = 0.f, lo = 0.f;
    df_prod_acc(hi, lo, v0.x, v0.x); df_prod_acc(hi, lo, v0.y, v0.y);
    df_prod_acc(hi, lo, v0.z, v0.z); df_prod_acc(hi, lo, v0.w, v0.w);
    df_prod_acc(hi, lo, v1.x, v1.x); df_prod_acc(hi, lo, v1.y, v1.y);
    df_prod_acc(hi, lo, v1.z, v1.z); df_prod_acc(hi, lo, v1.w, v1.w);
    #pragma unroll
    for (int ofs = 16; ofs; ofs >>= 1) {
        float oh = __shfl_xor_sync(0xffffffffu, hi, ofs);
        float ol = __shfl_xor_sync(0xffffffffu, lo, ofs);
        df_join(hi, lo, oh, ol);
    }
    int w = tid >> 5;
    if (!lane) { sh_h[w] = hi; sh_l[w] = lo; }
    __syncthreads();
    if (tid < 4) {                 // 4 rows per block, 2 warps each
        float h1 = sh_h[tid*2], l1 = sh_l[tid*2];
        float h2 = sh_h[tid*2+1], l2 = sh_l[tid*2+1];
        df_join(h1, l1, h2, l2);
        double d = (double)h1 + (double)l1;
        int row = blockIdx.x*4 + tid;
        g_sqd[row] = d;
        g_sq[row]  = (float)d;
    }
}

// ---------------- 2. zero the adjacency region ----------------
__global__ void zero_kernel(float4* __restrict__ p, long n4) {
    long i = blockIdx.x * (long)blockDim.x + threadIdx.x;
    long stride = gridDim.x * (long)blockDim.x;
    float4 z = make_float4(0.f, 0.f, 0.f, 0.f);
    for (; i < n4; i += stride) p[i] = z;
}

// ---------------- 3. symmetric bf16 GEMM + dual-direction top-12 (packed keys) ----------------
#define LDK 40                 // smem row stride in bf16 for tiles (80B)
#define LDD 132                // smem row stride in floats for d2 tile (528B, 16B aligned)
#define STAGE_B 20480          // bytes per stage (A 10240 + B 10240)
#define NSTAGE 4
#define DSMEM_BYTES (NSTAGE*STAGE_B)   // 81920 >= 128*132*4 = 67584 epilogue

__global__ __launch_bounds__(256) void gemm_topk_kernel() {
    extern __shared__ __align__(16) char dyn[];
    __shared__ __align__(16) float sqAh[128], sqBh[128];   // 0.5 * sq-norm

    // decode upper-triangular tile (mt, nt), nt >= mt
    int u = blockIdx.x, bz = blockIdx.z;
    int mt = (int)floorf(64.5f - sqrtf(64.5f*64.5f - 2.0f*(float)u));
    while ((mt+1)*(129-(mt+1))/2 <= u) mt++;
    while (mt*(129-mt)/2 > u) mt--;
    int nt = mt + (u - mt*(129-mt)/2);

    int tid = threadIdx.x;
    int lane = tid & 31, wid = tid >> 5;
    int wm = wid >> 1, wn = wid & 1;

    const __nv_bfloat16* Ag = g_fb + ((long)bz*NROWS + mt*TIL) * FDIM;
    const __nv_bfloat16* Bg = g_fb + ((long)bz*NROWS + nt*TIL) * FDIM;
    const uint4* A4 = (const uint4*)Ag;     // row = 64 uint4
    const uint4* B4 = (const uint4*)Bg;

    if (tid < 128) sqAh[tid] = 0.5f * g_sq[bz*NROWS + mt*TIL + tid];
    else           sqBh[tid-128] = 0.5f * g_sq[bz*NROWS + nt*TIL + (tid-128)];

    int r0c = tid >> 2,         c0c = tid & 3;
    int r1c = (tid + 256) >> 2, c1c = (tid + 256) & 3;
    unsigned dynb = (unsigned)__cvta_generic_to_shared(dyn);
    unsigned dA0 = r0c*80 + c0c*16, dA1 = r1c*80 + c1c*16;

    float acc[2][8][4];
    #pragma unroll
    for (int a = 0; a < 2; a++)
        #pragma unroll
        for (int b = 0; b < 8; b++)
            #pragma unroll
            for (int c = 0; c < 4; c++) acc[a][b][c] = 0.f;

    #pragma unroll
    for (int s = 0; s < NSTAGE-1; s++) {
        unsigned sb = dynb + s*STAGE_B;
        cpa16(sb + dA0,         A4 + (r0c*64 + s*4 + c0c));
        cpa16(sb + dA1,         A4 + (r1c*64 + s*4 + c1c));
        cpa16(sb + 10240 + dA0, B4 + (r0c*64 + s*4 + c0c));
        cpa16(sb + 10240 + dA1, B4 + (r1c*64 + s*4 + c1c));
        asm volatile("cp.async.commit_group;\n" ::);
    }

    // precomputed smem byte offsets (within a stage) for ldmatrix
    int arow = wm*32 + (lane & 15);
    int acol = (lane >> 4) * 8;
    int brow = wn*64 + (lane & 7) + (lane >> 4) * 8;
    int bcol = ((lane >> 3) & 1) * 8;
    unsigned aoff = dynb + (unsigned)(arow*LDK + acol)*2;
    unsigned boff = dynb + 10240u + (unsigned)(brow*LDK + bcol)*2;

    #pragma unroll 4
    for (int kk = 0; kk < 16; kk++) {
        asm volatile("cp.async.wait_group 2;\n" ::);
        __syncthreads();
        unsigned sbase = (kk & (NSTAGE-1)) * STAGE_B;

        #pragma unroll
        for (int ks = 0; ks < 2; ks++) {
            unsigned kb = ks * 32;   // 16 bf16 = 32B
            uint32_t a[2][4];
            #pragma unroll
            for (int mi = 0; mi < 2; mi++) {
                unsigned ad = aoff + sbase + kb + mi*(16*LDK*2);
                asm volatile("ldmatrix.sync.aligned.m8n8.x4.shared.b16 {%0,%1,%2,%3},[%4];"
                    : "=r"(a[mi][0]),"=r"(a[mi][1]),"=r"(a[mi][2]),"=r"(a[mi][3]) : "r"(ad));
            }
            uint32_t b[8][2];
            #pragma unroll
            for (int p = 0; p < 4; p++) {
                unsigned bad = boff + sbase + kb + p*(16*LDK*2);
                uint32_t r0, r1, r2, r3;
                asm volatile("ldmatrix.sync.aligned.m8n8.x4.shared.b16 {%0,%1,%2,%3},[%4];"
                    : "=r"(r0),"=r"(r1),"=r"(r2),"=r"(r3) : "r"(bad));
                b[2*p][0]=r0; b[2*p][1]=r1; b[2*p+1][0]=r2; b[2*p+1][1]=r3;
            }
            #pragma unroll
            for (int mi = 0; mi < 2; mi++)
                #pragma unroll
                for (int ni = 0; ni < 8; ni++)
                    asm volatile(
                        "mma.sync.aligned.m16n8k16.row.col.f32.bf16.bf16.f32 "
                        "{%0,%1,%2,%3},{%4,%5,%6,%7},{%8,%9},{%0,%1,%2,%3};"
                        : "+f"(acc[mi][ni][0]),"+f"(acc[mi][ni][1]),
                          "+f"(acc[mi][ni][2]),"+f"(acc[mi][ni][3])
                        : "r"(a[mi][0]),"r"(a[mi][1]),"r"(a[mi][2]),"r"(a[mi][3]),
                          "r"(b[ni][0]),"r"(b[ni][1]));
        }
        if (kk < 13) {
            int s = kk + 3;
            unsigned sb = dynb + (s & (NSTAGE-1))*STAGE_B;
            cpa16(sb + dA0,         A4 + (r0c*64 + s*4 + c0c));
            cpa16(sb + dA1,         A4 + (r1c*64 + s*4 + c1c));
            cpa16(sb + 10240 + dA0, B4 + (r0c*64 + s*4 + c0c));
            cpa16(sb + 10240 + dA1, B4 + (r1c*64 + s*4 + c1c));
        }
        asm volatile("cp.async.commit_group;\n" ::);
    }

    // ---- write full 128x132 dot tile ----
    __syncthreads();
    float* smd = (float*)dyn;
    {
        int g = lane >> 2, tg = lane & 3;
        #pragma unroll
        for (int mi = 0; mi < 2; mi++)
            #pragma unroll
            for (int ni = 0; ni < 8; ni++) {
                int r0 = wm*32 + mi*16 + g;
                int c0 = wn*64 + ni*8 + tg*2;
                smd[r0*LDD + c0]       = acc[mi][ni][0];
                smd[r0*LDD + c0 + 1]   = acc[mi][ni][1];
                smd[(r0+8)*LDD + c0]     = acc[mi][ni][2];
                smd[(r0+8)*LDD + c0 + 1] = acc[mi][ni][3];
            }
    }
    __syncthreads();

    // ---- selection: key v' = 0.5*sq[c] - dot ; top-12 per direction ----
    int rc = tid & 127;
    float bd[CAND_K]; int bi[CAND_K];
    #pragma unroll
    for (int q = 0; q < CAND_K; q++) { bd[q] = finf(); bi[q] = 0; }

    if (tid < 128) {                       // row-scan: rows of block mt vs cols of nt
        bool diag = (nt == mt);
        const float4* rp = (const float4*)(smd + rc*LDD);
        const float4* hb = (const float4*)sqBh;
        #pragma unroll 4
        for (int j4 = 0; j4 < 32; j4++) {
            float4 d = rp[j4];
            float4 h = hb[j4];
            float k0 = h.x - d.x, k1 = h.y - d.y, k2 = h.z - d.z, k3 = h.w - d.w;
            float m = fminf(fminf(k0,k1), fminf(k2,k3));
            if (m < bd[CAND_K-1]) {
                float kv[4] = {k0,k1,k2,k3};
                #pragma unroll
                for (int q4 = 0; q4 < 4; q4++) {
                    int col = j4*4 + q4;
                    float v = kv[q4];
                    if (v < bd[CAND_K-1] && !(diag && col == rc)) {
                        bd[CAND_K-1] = v; bi[CAND_K-1] = nt*TIL + col;
                        #pragma unroll
                        for (int q = CAND_K-1; q > 0; q--)
                            if (bd[q] < bd[q-1]) {
                                float td = bd[q]; bd[q] = bd[q-1]; bd[q-1] = td;
                                int   ti = bi[q]; bi[q] = bi[q-1]; bi[q-1] = ti;
                            }
                    }
                }
            }
        }
        long base = (((long)(bz*NROWS + mt*TIL + rc))*NTILES + nt)*CAND_K;
        ulonglong2* dst = (ulonglong2*)(g_ck + base);
        #pragma unroll
        for (int i = 0; i < 6; i++)
            dst[i] = make_ulonglong2(packkey(bd[2*i], bi[2*i]),
                                     packkey(bd[2*i+1], bi[2*i+1]));
    } else if (nt != mt) {                 // col-scan: rows of block nt vs cols of mt
        #pragma unroll 4
        for (int r4 = 0; r4 < 32; r4++) {
            float k0 = sqAh[4*r4+0] - smd[(4*r4+0)*LDD + rc];
            float k1 = sqAh[4*r4+1] - smd[(4*r4+1)*LDD + rc];
            float k2 = sqAh[4*r4+2] - smd[(4*r4+2)*LDD + rc];
            float k3 = sqAh[4*r4+3] - smd[(4*r4+3)*LDD + rc];
            float m = fminf(fminf(k0,k1), fminf(k2,k3));
            if (m < bd[CAND_K-1]) {
                float kv[4] = {k0,k1,k2,k3};
                #pragma unroll
                for (int q4 = 0; q4 < 4; q4++) {
                    float v = kv[q4];
                    if (v < bd[CAND_K-1]) {
                        bd[CAND_K-1] = v; bi[CAND_K-1] = mt*TIL + r4*4 + q4;
                        #pragma unroll
                        for (int q = CAND_K-1; q > 0; q--)
                            if (bd[q] < bd[q-1]) {
                                float td = bd[q]; bd[q] = bd[q-1]; bd[q-1] = td;
                                int   ti = bi[q]; bi[q] = bi[q-1]; bi[q-1] = ti;
                            }
                    }
                }
            }
        }
        long base = (((long)(bz*NROWS + nt*TIL + rc))*NTILES + mt)*CAND_K;
        ulonglong2* dst = (ulonglong2*)(g_ck + base);
        #pragma unroll
        for (int i = 0; i < 6; i++)
            dst[i] = make_ulonglong2(packkey(bd[2*i], bi[2*i]),
                                     packkey(bd[2*i+1], bi[2*i+1]));
    }
}

// ---------------- 4. fused merge (warp/row) + df64 refine + scatter ----------------
__global__ __launch_bounds__(256) void merge_refine_kernel(
        const float* __restrict__ feats, float* __restrict__ adj) {
    int gw = (blockIdx.x * blockDim.x + threadIdx.x) >> 5;   // row id 0..16383
    int lane = threadIdx.x & 31;
    int bz = gw >> 13, rl = gw & 8191;

    // ---- lane loads its 2 adjacent tile-slots (24 packed cands, 12 x 16B) ----
    unsigned long long A[12], B[12];
    {
        const ulonglong2* p = (const ulonglong2*)
            (g_ck + ((long)gw*NTILES + lane*2)*CAND_K);
        ulonglong2 v0=p[0],v1=p[1],v2=p[2],v3=p[3],v4=p[4],v5=p[5];
        ulonglong2 w0=p[6],w1=p[7],w2=p[8],w3=p[9],w4=p[10],w5=p[11];
        A[0]=v0.x;A[1]=v0.y;A[2]=v1.x;A[3]=v1.y;A[4]=v2.x;A[5]=v2.y;
        A[6]=v3.x;A[7]=v3.y;A[8]=v4.x;A[9]=v4.y;A[10]=v5.x;A[11]=v5.y;
        B[0]=w0.x;B[1]=w0.y;B[2]=w1.x;B[3]=w1.y;B[4]=w2.x;B[5]=w2.y;
        B[6]=w3.x;B[7]=w3.y;B[8]=w4.x;B[9]=w4.y;B[10]=w5.x;B[11]=w5.y;
    }
    // ---- local top-16: seed with sorted run A, insert sorted run B ----
    unsigned long long bd[16];
    #pragma unroll
    for (int q = 0; q < 12; q++) bd[q] = A[q];
    bd[12] = bd[13] = bd[14] = bd[15] = ~0ull;
    #pragma unroll
    for (int q = 0; q < 12; q++) {
        unsigned long long v = B[q];
        if (v >= bd[15]) break;                  // B sorted ascending
        bd[15] = v;
        #pragma unroll
        for (int qq = 15; qq > 0; qq--)
            if (bd[qq] < bd[qq-1]) {
                unsigned long long t = bd[qq]; bd[qq] = bd[qq-1]; bd[qq-1] = t;
            }
    }

    // ---- warp pop-merge: global top-16, candidate k -> lane k ----
    int myci = 0;
    #pragma unroll 1
    for (int k = 0; k < 16; k++) {
        unsigned long long v = bd[0];
        #pragma unroll
        for (int o = 16; o; o >>= 1) {
            unsigned long long ov = __shfl_xor_sync(0xffffffffu, v, o);
            if (ov < v) v = ov;
        }
        if (lane == k) myci = (int)(v & 8191u);
        if (bd[0] == v) {                        // keys unique: one popper
            #pragma unroll
            for (int q = 0; q < 15; q++) bd[q] = bd[q+1];
            bd[15] = ~0ull;
        }
    }

    // ---- df64 exact refine of the 16 candidates ----
    const float4* fr4 = (const float4*)(feats + (long)gw*FDIM);
    float4 R[4];
    #pragma unroll
    for (int i = 0; i < 4; i++) R[i] = fr4[lane*4 + i];
    double sqr = g_sqd[gw];

    double myd2 = __longlong_as_double(0x7ff0000000000000ll);
    int myidx = 0x7fffffff;

    #pragma unroll 2
    for (int c = 0; c < 16; c++) {
        int ci = __shfl_sync(0xffffffffu, myci, c);
        const float4* fc4 = (const float4*)(feats + ((long)bz*NROWS + ci)*FDIM);
        float hi = 0.f, lo = 0.f;
        #pragma unroll
        for (int i = 0; i < 4; i++) {
            float4 fv = fc4[lane*4 + i];
            df_prod_acc(hi, lo, R[i].x, fv.x);
            df_prod_acc(hi, lo, R[i].y, fv.y);
            df_prod_acc(hi, lo, R[i].z, fv.z);
            df_prod_acc(hi, lo, R[i].w, fv.w);
        }
        #pragma unroll
        for (int o = 16; o; o >>= 1) {
            float oh = __shfl_xor_sync(0xffffffffu, hi, o);
            float ol = __shfl_xor_sync(0xffffffffu, lo, o);
            df_join(hi, lo, oh, ol);
        }
        double dot = (double)hi + (double)lo;
        double d2 = sqr + g_sqd[bz*NROWS + ci] - 2.0*dot;
        if (lane == c) { myd2 = d2; myidx = ci; }
    }

    // ---- top-8 select (idx tiebreak) + symmetric scatter ----
    long adjbase = (long)bz * NROWS * NROWS;
    #pragma unroll 1
    for (int k = 0; k < 8; k++) {
        double bdv = myd2; int biv = myidx;
        #pragma unroll
        for (int o = 16; o; o >>= 1) {
            double od = __shfl_xor_sync(0xffffffffu, bdv, o);
            int    oi = __shfl_xor_sync(0xffffffffu, biv, o);
            if (od < bdv || (od == bdv && oi < biv)) { bdv = od; biv = oi; }
        }
        if (myidx == biv) {
            myd2 = __longlong_as_double(0x7ff0000000000000ll);
            myidx = 0x7fffffff;
        }
        if (lane == k) {
            atomicAdd(adj + adjbase + (long)rl*NROWS + biv, 0.5f);
            atomicAdd(adj + adjbase + (long)biv*NROWS + rl, 0.5f);
        }
    }
}

// ---------------- launch ----------------
extern "C" void kernel_launch(void* const* d_in, const int* in_sizes, int n_in,
                              void* d_out, int out_size) {
    const float* img = (const float*)d_in[0];   // [2,1,256,256,64] fp32; d_in[1]=n (8)
    float* feats = (float*)d_out;                       // [2,8192,512]
    float* adj   = feats + FEATS_ELEMS;                 // [2,8192,8192]

    cudaFuncSetAttribute(gemm_topk_kernel,
                         cudaFuncAttributeMaxDynamicSharedMemorySize, DSMEM_BYTES);

    patch_kernel<<<4096, 256>>>(img, feats);
    zero_kernel<<<16384, 256>>>((float4*)adj, ADJ_ELEMS/4);
    dim3 gg(NUTRI, 1, NB);
    gemm_topk_kernel<<<gg, 256, DSMEM_BYTES>>>();
    merge_refine_kernel<<<2048, 256>>>(feats, adj);
}

// round 7
// speedup vs baseline: 2.8494x; 1.0174x over previous
#include <cuda_runtime.h>
#include <cuda_bf16.h>
#include <cstdint>

#define NB 2
#define NROWS 8192
#define FDIM 512
#define TIL 128
#define NTILES 64      // 8192/128
#define CAND_K 12      // top-12 per 128-col tile
#define NUTRI 2080     // 64*65/2 upper-triangular tiles
#define FEATS_ELEMS ((long)NB*NROWS*FDIM)          // 8388608
#define ADJ_ELEMS   ((long)NB*NROWS*NROWS)         // 134217728
#define ADJ4        (ADJ_ELEMS/4)                  // 33554432 float4s
#define Z_PER_CTA   8067                           // ceil(ADJ4 / (NUTRI*NB))

// ---------------- scratch (device globals: allowed) ----------------
__device__ __align__(16) __nv_bfloat16 g_fb[NB*NROWS*FDIM];          // 16MB bf16 feats
__device__ float  g_sq[NB*NROWS];                                    // fp32 sq norms
__device__ double g_sqd[NB*NROWS];                                   // exact sq norms (refine)
__device__ unsigned long long g_ck[(long)NB*NROWS*NTILES*CAND_K];    // 100MB packed cand

__device__ __forceinline__ float finf() { return __int_as_float(0x7f800000); }

__device__ __forceinline__ void cpa16(unsigned d, const void* s) {
    asm volatile("cp.async.cg.shared.global [%0], [%1], 16;\n" :: "r"(d), "l"(s));
}

__device__ __forceinline__ unsigned long long packkey(float k, int col) {
    unsigned u = __float_as_uint(k);
    u ^= (unsigned)((int)u >> 31) | 0x80000000u;   // orderable-uint transform
    return ((unsigned long long)u << 13) | (unsigned)col;
}

// df64 helpers — rounding-mode intrinsics so fast-math can't fold them
__device__ __forceinline__ void df_acc(float& hi, float& lo, float p) {
    float s  = __fadd_rn(hi, p);
    float t  = __fsub_rn(s, hi);
    float er = __fadd_rn(__fsub_rn(hi, __fsub_rn(s, t)), __fsub_rn(p, t));
    hi = s; lo = __fadd_rn(lo, er);
}
__device__ __forceinline__ void df_prod_acc(float& hi, float& lo, float a, float b) {
    float p = __fmul_rn(a, b);
    float e = __fmaf_rn(a, b, -p);
    df_acc(hi, lo, p);
    lo = __fadd_rn(lo, e);
}
__device__ __forceinline__ void df_join(float& hi, float& lo, float oh, float ol) {
    float s  = __fadd_rn(hi, oh);
    float t  = __fsub_rn(s, hi);
    float er = __fadd_rn(__fsub_rn(hi, __fsub_rn(s, t)), __fsub_rn(oh, t));
    hi = s; lo = __fadd_rn(lo, __fadd_rn(ol, er));
}

// ---------------- 1. patch extraction + fused exact sqnorm ----------------
__global__ void patch_kernel(const float* __restrict__ img, float* __restrict__ feats) {
    __shared__ float sh_h[8], sh_l[8];
    int idx = blockIdx.x * blockDim.x + threadIdx.x;
    int tid = threadIdx.x, lane = tid & 31;
    int fc = idx & 63;
    int t  = idx >> 6;
    int p  = t & 8191;
    int b  = t >> 13;
    int ph = fc >> 3, pw = fc & 7;
    int db = p & 7, wb = (p >> 3) & 31, hb = p >> 8;
    const float4* src = (const float4*)(img + (long)b*4194304
                          + (long)(hb*8+ph)*16384 + (long)(wb*8+pw)*64 + db*8);
    float4 v0 = src[0], v1 = src[1];
    long o = (long)t*FDIM + fc*8;
    float4* dst = (float4*)(feats + o);
    dst[0] = v0; dst[1] = v1;
    __nv_bfloat162* bp = (__nv_bfloat162*)(g_fb + o);
    bp[0] = __floats2bfloat162_rn(v0.x, v0.y);
    bp[1] = __floats2bfloat162_rn(v0.z, v0.w);
    bp[2] = __floats2bfloat162_rn(v1.x, v1.y);
    bp[3] = __floats2bfloat162_rn(v1.z, v1.w);

    float hi = 0.f, lo = 0.f;
    df_prod_acc(hi, lo, v0.x, v0.x); df_prod_acc(hi, lo, v0.y, v0.y);
    df_prod_acc(hi, lo, v0.z, v0.z); df_prod_acc(hi, lo, v0.w, v0.w);
    df_prod_acc(hi, lo, v1.x, v1.x); df_prod_acc(hi, lo, v1.y, v1.y);
    df_prod_acc(hi, lo, v1.z, v1.z); df_prod_acc(hi, lo, v1.w, v1.w);
    #pragma unroll
    for (int ofs = 16; ofs; ofs >>= 1) {
        float oh = __shfl_xor_sync(0xffffffffu, hi, ofs);
        float ol = __shfl_xor_sync(0xffffffffu, lo, ofs);
        df_join(hi, lo, oh, ol);
    }
    int w = tid >> 5;
    if (!lane) { sh_h[w] = hi; sh_l[w] = lo; }
    __syncthreads();
    if (tid < 4) {
        float h1 = sh_h[tid*2], l1 = sh_l[tid*2];
        float h2 = sh_h[tid*2+1], l2 = sh_l[tid*2+1];
        df_join(h1, l1, h2, l2);
        double d = (double)h1 + (double)l1;
        int row = blockIdx.x*4 + tid;
        g_sqd[row] = d;
        g_sq[row]  = (float)d;
    }
}

// ---------------- 2. symmetric bf16 GEMM + fused zero-adj + dual top-12 ----------------
#define LDK 40                 // smem row stride in bf16 for tiles (80B)
#define LDD 132                // smem row stride in floats for d2 tile
#define STAGE_B 20480          // bytes per stage (A 10240 + B 10240)
#define NSTAGE 4
#define DSMEM_BYTES (NSTAGE*STAGE_B)   // 81920 >= 128*132*4 = 67584 epilogue

__global__ __launch_bounds__(256) void gemm_topk_kernel(float* __restrict__ adj) {
    extern __shared__ __align__(16) char dyn[];
    __shared__ __align__(16) float sqAh[128], sqBh[128];   // 0.5 * sq-norm

    // decode upper-triangular tile (mt, nt), nt >= mt
    int u = blockIdx.x, bz = blockIdx.z;
    int mt = (int)floorf(64.5f - sqrtf(64.5f*64.5f - 2.0f*(float)u));
    while ((mt+1)*(129-(mt+1))/2 <= u) mt++;
    while (mt*(129-mt)/2 > u) mt--;
    int nt = mt + (u - mt*(129-mt)/2);

    int tid = threadIdx.x;
    int lane = tid & 31, wid = tid >> 5;
    int wm = wid >> 1, wn = wid & 1;

    const __nv_bfloat16* Ag = g_fb + ((long)bz*NROWS + mt*TIL) * FDIM;
    const __nv_bfloat16* Bg = g_fb + ((long)bz*NROWS + nt*TIL) * FDIM;
    const uint4* A4 = (const uint4*)Ag;     // row = 64 uint4
    const uint4* B4 = (const uint4*)Bg;

    if (tid < 128) sqAh[tid] = 0.5f * g_sq[bz*NROWS + mt*TIL + tid];
    else           sqBh[tid-128] = 0.5f * g_sq[bz*NROWS + nt*TIL + (tid-128)];

    int r0c = tid >> 2,         c0c = tid & 3;
    int r1c = (tid + 256) >> 2, c1c = (tid + 256) & 3;
    unsigned dynb = (unsigned)__cvta_generic_to_shared(dyn);
    unsigned dA0 = r0c*80 + c0c*16, dA1 = r1c*80 + c1c*16;

    float acc[2][8][4];
    #pragma unroll
    for (int a = 0; a < 2; a++)
        #pragma unroll
        for (int b = 0; b < 8; b++)
            #pragma unroll
            for (int c = 0; c < 4; c++) acc[a][b][c] = 0.f;

    #pragma unroll
    for (int s = 0; s < NSTAGE-1; s++) {
        unsigned sb = dynb + s*STAGE_B;
        cpa16(sb + dA0,         A4 + (r0c*64 + s*4 + c0c));
        cpa16(sb + dA1,         A4 + (r1c*64 + s*4 + c1c));
        cpa16(sb + 10240 + dA0, B4 + (r0c*64 + s*4 + c0c));
        cpa16(sb + 10240 + dA1, B4 + (r1c*64 + s*4 + c1c));
        asm volatile("cp.async.commit_group;\n" ::);
    }

    // fused zero of this CTA's adjacency slice — overlaps the pipeline / mainloop
    {
        long cta = (long)bz*NUTRI + u;
        long s0 = cta * Z_PER_CTA;
        long e0 = s0 + Z_PER_CTA; if (e0 > ADJ4) e0 = ADJ4;
        float4 z = make_float4(0.f, 0.f, 0.f, 0.f);
        float4* ap = (float4*)adj;
        for (long i = s0 + tid; i < e0; i += 256) ap[i] = z;
    }

    // precomputed smem byte offsets (within a stage) for ldmatrix
    int arow = wm*32 + (lane & 15);
    int acol = (lane >> 4) * 8;
    int brow = wn*64 + (lane & 7) + (lane >> 4) * 8;
    int bcol = ((lane >> 3) & 1) * 8;
    unsigned aoff = dynb + (unsigned)(arow*LDK + acol)*2;
    unsigned boff = dynb + 10240u + (unsigned)(brow*LDK + bcol)*2;

    #pragma unroll 4
    for (int kk = 0; kk < 16; kk++) {
        asm volatile("cp.async.wait_group 2;\n" ::);
        __syncthreads();
        unsigned sbase = (kk & (NSTAGE-1)) * STAGE_B;

        #pragma unroll
        for (int ks = 0; ks < 2; ks++) {
            unsigned kb = ks * 32;   // 16 bf16 = 32B
            uint32_t a[2][4];
            #pragma unroll
            for (int mi = 0; mi < 2; mi++) {
                unsigned ad = aoff + sbase + kb + mi*(16*LDK*2);
                asm volatile("ldmatrix.sync.aligned.m8n8.x4.shared.b16 {%0,%1,%2,%3},[%4];"
                    : "=r"(a[mi][0]),"=r"(a[mi][1]),"=r"(a[mi][2]),"=r"(a[mi][3]) : "r"(ad));
            }
            uint32_t b[8][2];
            #pragma unroll
            for (int p = 0; p < 4; p++) {
                unsigned bad = boff + sbase + kb + p*(16*LDK*2);
                uint32_t r0, r1, r2, r3;
                asm volatile("ldmatrix.sync.aligned.m8n8.x4.shared.b16 {%0,%1,%2,%3},[%4];"
                    : "=r"(r0),"=r"(r1),"=r"(r2),"=r"(r3) : "r"(bad));
                b[2*p][0]=r0; b[2*p][1]=r1; b[2*p+1][0]=r2; b[2*p+1][1]=r3;
            }
            #pragma unroll
            for (int mi = 0; mi < 2; mi++)
                #pragma unroll
                for (int ni = 0; ni < 8; ni++)
                    asm volatile(
                        "mma.sync.aligned.m16n8k16.row.col.f32.bf16.bf16.f32 "
                        "{%0,%1,%2,%3},{%4,%5,%6,%7},{%8,%9},{%0,%1,%2,%3};"
                        : "+f"(acc[mi][ni][0]),"+f"(acc[mi][ni][1]),
                          "+f"(acc[mi][ni][2]),"+f"(acc[mi][ni][3])
                        : "r"(a[mi][0]),"r"(a[mi][1]),"r"(a[mi][2]),"r"(a[mi][3]),
                          "r"(b[ni][0]),"r"(b[ni][1]));
        }
        if (kk < 13) {
            int s = kk + 3;
            unsigned sb = dynb + (s & (NSTAGE-1))*STAGE_B;
            cpa16(sb + dA0,         A4 + (r0c*64 + s*4 + c0c));
            cpa16(sb + dA1,         A4 + (r1c*64 + s*4 + c1c));
            cpa16(sb + 10240 + dA0, B4 + (r0c*64 + s*4 + c0c));
            cpa16(sb + 10240 + dA1, B4 + (r1c*64 + s*4 + c1c));
        }
        asm volatile("cp.async.commit_group;\n" ::);
    }

    // ---- write full 128x132 dot tile ----
    __syncthreads();
    float* smd = (float*)dyn;
    {
        int g = lane >> 2, tg = lane & 3;
        #pragma unroll
        for (int mi = 0; mi < 2; mi++)
            #pragma unroll
            for (int ni = 0; ni < 8; ni++) {
                int r0 = wm*32 + mi*16 + g;
                int c0 = wn*64 + ni*8 + tg*2;
                smd[r0*LDD + c0]       = acc[mi][ni][0];
                smd[r0*LDD + c0 + 1]   = acc[mi][ni][1];
                smd[(r0+8)*LDD + c0]     = acc[mi][ni][2];
                smd[(r0+8)*LDD + c0 + 1] = acc[mi][ni][3];
            }
    }
    __syncthreads();

    // ---- selection: key v' = 0.5*sq[c] - dot ; top-12 per direction ----
    int rc = tid & 127;
    float bd[CAND_K]; int bi[CAND_K];
    #pragma unroll
    for (int q = 0; q < CAND_K; q++) { bd[q] = finf(); bi[q] = 0; }

    if (tid < 128) {                       // row-scan: rows of block mt vs cols of nt
        bool diag = (nt == mt);
        const float4* rp = (const float4*)(smd + rc*LDD);
        const float4* hb = (const float4*)sqBh;
        #pragma unroll 4
        for (int j4 = 0; j4 < 32; j4++) {
            float4 d = rp[j4];
            float4 h = hb[j4];
            float k0 = h.x - d.x, k1 = h.y - d.y, k2 = h.z - d.z, k3 = h.w - d.w;
            float m = fminf(fminf(k0,k1), fminf(k2,k3));
            if (m < bd[CAND_K-1]) {
                float kv[4] = {k0,k1,k2,k3};
                #pragma unroll
                for (int q4 = 0; q4 < 4; q4++) {
                    int col = j4*4 + q4;
                    float v = kv[q4];
                    if (v < bd[CAND_K-1] && !(diag && col == rc)) {
                        bd[CAND_K-1] = v; bi[CAND_K-1] = nt*TIL + col;
                        #pragma unroll
                        for (int q = CAND_K-1; q > 0; q--)
                            if (bd[q] < bd[q-1]) {
                                float td = bd[q]; bd[q] = bd[q-1]; bd[q-1] = td;
                                int   ti = bi[q]; bi[q] = bi[q-1]; bi[q-1] = ti;
                            }
                    }
                }
            }
        }
        long base = (((long)(bz*NROWS + mt*TIL + rc))*NTILES + nt)*CAND_K;
        ulonglong2* dst = (ulonglong2*)(g_ck + base);
        #pragma unroll
        for (int i = 0; i < 6; i++)
            dst[i] = make_ulonglong2(packkey(bd[2*i], bi[2*i]),
                                     packkey(bd[2*i+1], bi[2*i+1]));
    } else if (nt != mt) {                 // col-scan: rows of block nt vs cols of mt
        #pragma unroll 4
        for (int r4 = 0; r4 < 32; r4++) {
            float k0 = sqAh[4*r4+0] - smd[(4*r4+0)*LDD + rc];
            float k1 = sqAh[4*r4+1] - smd[(4*r4+1)*LDD + rc];
            float k2 = sqAh[4*r4+2] - smd[(4*r4+2)*LDD + rc];
            float k3 = sqAh[4*r4+3] - smd[(4*r4+3)*LDD + rc];
            float m = fminf(fminf(k0,k1), fminf(k2,k3));
            if (m < bd[CAND_K-1]) {
                float kv[4] = {k0,k1,k2,k3};
                #pragma unroll
                for (int q4 = 0; q4 < 4; q4++) {
                    float v = kv[q4];
                    if (v < bd[CAND_K-1]) {
                        bd[CAND_K-1] = v; bi[CAND_K-1] = mt*TIL + r4*4 + q4;
                        #pragma unroll
                        for (int q = CAND_K-1; q > 0; q--)
                            if (bd[q] < bd[q-1]) {
                                float td = bd[q]; bd[q] = bd[q-1]; bd[q-1] = td;
                                int   ti = bi[q]; bi[q] = bi[q-1]; bi[q-1] = ti;
                            }
                    }
                }
            }
        }
        long base = (((long)(bz*NROWS + nt*TIL + rc))*NTILES + mt)*CAND_K;
        ulonglong2* dst = (ulonglong2*)(g_ck + base);
        #pragma unroll
        for (int i = 0; i < 6; i++)
            dst[i] = make_ulonglong2(packkey(bd[2*i], bi[2*i]),
                                     packkey(bd[2*i+1], bi[2*i+1]));
    }
}

// ---------------- 3. fused merge (warp/row) + df64 refine + scatter ----------------
__global__ __launch_bounds__(256) void merge_refine_kernel(
        const float* __restrict__ feats, float* __restrict__ adj) {
    int gw = (blockIdx.x * blockDim.x + threadIdx.x) >> 5;   // row id 0..16383
    int lane = threadIdx.x & 31;
    int bz = gw >> 13, rl = gw & 8191;

    unsigned long long A[12], B[12];
    {
        const ulonglong2* p = (const ulonglong2*)
            (g_ck + ((long)gw*NTILES + lane*2)*CAND_K);
        ulonglong2 v0=p[0],v1=p[1],v2=p[2],v3=p[3],v4=p[4],v5=p[5];
        ulonglong2 w0=p[6],w1=p[7],w2=p[8],w3=p[9],w4=p[10],w5=p[11];
        A[0]=v0.x;A[1]=v0.y;A[2]=v1.x;A[3]=v1.y;A[4]=v2.x;A[5]=v2.y;
        A[6]=v3.x;A[7]=v3.y;A[8]=v4.x;A[9]=v4.y;A[10]=v5.x;A[11]=v5.y;
        B[0]=w0.x;B[1]=w0.y;B[2]=w1.x;B[3]=w1.y;B[4]=w2.x;B[5]=w2.y;
        B[6]=w3.x;B[7]=w3.y;B[8]=w4.x;B[9]=w4.y;B[10]=w5.x;B[11]=w5.y;
    }
    unsigned long long bd[16];
    #pragma unroll
    for (int q = 0; q < 12; q++) bd[q] = A[q];
    bd[12] = bd[13] = bd[14] = bd[15] = ~0ull;
    #pragma unroll
    for (int q = 0; q < 12; q++) {
        unsigned long long v = B[q];
        if (v >= bd[15]) break;
        bd[15] = v;
        #pragma unroll
        for (int qq = 15; qq > 0; qq--)
            if (bd[qq] < bd[qq-1]) {
                unsigned long long t = bd[qq]; bd[qq] = bd[qq-1]; bd[qq-1] = t;
            }
    }

    int myci = 0;
    #pragma unroll 1
    for (int k = 0; k < 16; k++) {
        unsigned long long v = bd[0];
        #pragma unroll
        for (int o = 16; o; o >>= 1) {
            unsigned long long ov = __shfl_xor_sync(0xffffffffu, v, o);
            if (ov < v) v = ov;
        }
        if (lane == k) myci = (int)(v & 8191u);
        if (bd[0] == v) {
            #pragma unroll
            for (int q = 0; q < 15; q++) bd[q] = bd[q+1];
            bd[15] = ~0ull;
        }
    }

    const float4* fr4 = (const float4*)(feats + (long)gw*FDIM);
    float4 R[4];
    #pragma unroll
    for (int i = 0; i < 4; i++) R[i] = fr4[lane*4 + i];
    double sqr = g_sqd[gw];

    double myd2 = __longlong_as_double(0x7ff0000000000000ll);
    int myidx = 0x7fffffff;

    #pragma unroll 2
    for (int c = 0; c < 16; c++) {
        int ci = __shfl_sync(0xffffffffu, myci, c);
        const float4* fc4 = (const float4*)(feats + ((long)bz*NROWS + ci)*FDIM);
        float hi = 0.f, lo = 0.f;
        #pragma unroll
        for (int i = 0; i < 4; i++) {
            float4 fv = fc4[lane*4 + i];
            df_prod_acc(hi, lo, R[i].x, fv.x);
            df_prod_acc(hi, lo, R[i].y, fv.y);
            df_prod_acc(hi, lo, R[i].z, fv.z);
            df_prod_acc(hi, lo, R[i].w, fv.w);
        }
        #pragma unroll
        for (int o = 16; o; o >>= 1) {
            float oh = __shfl_xor_sync(0xffffffffu, hi, o);
            float ol = __shfl_xor_sync(0xffffffffu, lo, o);
            df_join(hi, lo, oh, ol);
        }
        double dot = (double)hi + (double)lo;
        double d2 = sqr + g_sqd[bz*NROWS + ci] - 2.0*dot;
        if (lane == c) { myd2 = d2; myidx = ci; }
    }

    long adjbase = (long)bz * NROWS * NROWS;
    #pragma unroll 1
    for (int k = 0; k < 8; k++) {
        double bdv = myd2; int biv = myidx;
        #pragma unroll
        for (int o = 16; o; o >>= 1) {
            double od = __shfl_xor_sync(0xffffffffu, bdv, o);
            int    oi = __shfl_xor_sync(0xffffffffu, biv, o);
            if (od < bdv || (od == bdv && oi < biv)) { bdv = od; biv = oi; }
        }
        if (myidx == biv) {
            myd2 = __longlong_as_double(0x7ff0000000000000ll);
            myidx = 0x7fffffff;
        }
        if (lane == k) {
            atomicAdd(adj + adjbase + (long)rl*NROWS + biv, 0.5f);
            atomicAdd(adj + adjbase + (long)biv*NROWS + rl, 0.5f);
        }
    }
}

// ---------------- launch ----------------
extern "C" void kernel_launch(void* const* d_in, const int* in_sizes, int n_in,
                              void* d_out, int out_size) {
    const float* img = (const float*)d_in[0];   // [2,1,256,256,64] fp32; d_in[1]=n (8)
    float* feats = (float*)d_out;                       // [2,8192,512]
    float* adj   = feats + FEATS_ELEMS;                 // [2,8192,8192]

    cudaFuncSetAttribute(gemm_topk_kernel,
                         cudaFuncAttributeMaxDynamicSharedMemorySize, DSMEM_BYTES);

    patch_kernel<<<4096, 256>>>(img, feats);
    dim3 gg(NUTRI, 1, NB);
    gemm_topk_kernel<<<gg, 256, DSMEM_BYTES>>>(adj);
    merge_refine_kernel<<<2048, 256>>>(feats, adj);
}